// round 6
// baseline (speedup 1.0000x reference)
#include <cuda_runtime.h>
#include <cuda_bf16.h>
#include <math.h>
#include <stdint.h>

#define BB 64
#define SS 2048
#define EE 512
#define HH 512
#define TT 128
#define MTOT (BB * SS)

// ---------------------------------------------------------------------------
// Scratch (__device__ globals; no allocation allowed)
// ---------------------------------------------------------------------------
__device__ float g_ctxsum[BB * 4 * EE];
__device__ float g_count[BB * 4];
__device__ float g_u[BB * HH];
__device__ float g_mask[MTOT];
__device__ float g_spart[4 * MTOT];
__device__ float g_attn[BB * SS];
__device__ float g_rep[BB * 8 * EE];
__device__ __nv_bfloat16 g_Wh[HH * EE];   // [n][k] = W_att[k][n], hi part
__device__ __nv_bfloat16 g_Wl[HH * EE];   // lo part
__device__ __nv_bfloat16 g_Ah[(size_t)MTOT * EE];  // words hi  (128 MB)
__device__ __nv_bfloat16 g_Al[(size_t)MTOT * EE];  // words lo  (128 MB)

// ---------------------------------------------------------------------------
// PTX helpers
// ---------------------------------------------------------------------------
__device__ __forceinline__ uint32_t smem_to_u32(const void* p) {
    uint32_t a;
    asm("{ .reg .u64 t; cvta.to.shared.u64 t, %1; cvt.u32.u64 %0, t; }"
        : "=r"(a) : "l"(p));
    return a;
}

__device__ __forceinline__ void ldsm_x4(uint32_t* r, uint32_t addr) {
    asm volatile("ldmatrix.sync.aligned.m8n8.x4.shared.b16 {%0,%1,%2,%3}, [%4];"
                 : "=r"(r[0]), "=r"(r[1]), "=r"(r[2]), "=r"(r[3]) : "r"(addr));
}

__device__ __forceinline__ void mma16816(float* c, const uint32_t* a, const uint32_t* b) {
    asm volatile(
        "mma.sync.aligned.m16n8k16.row.col.f32.bf16.bf16.f32 "
        "{%0,%1,%2,%3}, {%4,%5,%6,%7}, {%8,%9}, {%0,%1,%2,%3};"
        : "+f"(c[0]), "+f"(c[1]), "+f"(c[2]), "+f"(c[3])
        : "r"(a[0]), "r"(a[1]), "r"(a[2]), "r"(a[3]), "r"(b[0]), "r"(b[1]));
}

__device__ __forceinline__ void cp16(uint32_t saddr, const void* g) {
    asm volatile("cp.async.cg.shared.global [%0], [%1], 16;" :: "r"(saddr), "l"(g));
}
#define CP_COMMIT() asm volatile("cp.async.commit_group;" ::: "memory")
template <int N>
__device__ __forceinline__ void cp_wait() {
    asm volatile("cp.async.wait_group %0;" :: "n"(N) : "memory");
}

// ---------------------------------------------------------------------------
// Kernel W: transpose + bf16 hi/lo split of W_att top half
// ---------------------------------------------------------------------------
__global__ void __launch_bounds__(512) wprep_kernel(const float* __restrict__ Watt) {
    const int n = blockIdx.x, k = threadIdx.x;
    float w = Watt[(size_t)k * HH + n];
    __nv_bfloat16 hi = __float2bfloat16_rn(w);
    float r = w - __bfloat162float(hi);
    g_Wh[(size_t)n * EE + k] = hi;
    g_Wl[(size_t)n * EE + k] = __float2bfloat16_rn(r);
}

// ---------------------------------------------------------------------------
// Kernel A (fused prep): colsums + counts + mask + bf16 hi/lo split of words
// ---------------------------------------------------------------------------
__global__ void __launch_bounds__(256) ctx_prep_kernel(const float* __restrict__ words) {
    __shared__ float part[8][EE];
    __shared__ float cnt_sm[8];
    const int tid = threadIdx.x;
    const int warp = tid >> 5, lane = tid & 31;
    const int blk = blockIdx.x;
    const int b = blk >> 2, c = blk & 3;
    const int row0 = b * SS + c * 512;
    const float* wbase = words + (size_t)row0 * EE;

    float creg[16];
#pragma unroll
    for (int j = 0; j < 16; ++j) creg[j] = 0.f;
    float cnt = 0.f;

    for (int r = warp; r < 512; r += 8) {
        const float4* row = (const float4*)(wbase + (size_t)r * EE);
        const size_t grow = (size_t)(row0 + r);
        float rs = 0.f;
#pragma unroll
        for (int j = 0; j < 4; ++j) {
            float4 x = row[j * 32 + lane];
            rs += x.x + x.y + x.z + x.w;
            creg[j * 4 + 0] += x.x;
            creg[j * 4 + 1] += x.y;
            creg[j * 4 + 2] += x.z;
            creg[j * 4 + 3] += x.w;
            __nv_bfloat162 h01 = __float22bfloat162_rn(make_float2(x.x, x.y));
            __nv_bfloat162 h23 = __float22bfloat162_rn(make_float2(x.z, x.w));
            __nv_bfloat162 l01 = __float22bfloat162_rn(
                make_float2(x.x - __bfloat162float(h01.x), x.y - __bfloat162float(h01.y)));
            __nv_bfloat162 l23 = __float22bfloat162_rn(
                make_float2(x.z - __bfloat162float(h23.x), x.w - __bfloat162float(h23.y)));
            const size_t idx = grow * EE + (size_t)(j * 32 + lane) * 4;
            *(uint2*)&g_Ah[idx] = make_uint2(*(uint32_t*)&h01, *(uint32_t*)&h23);
            *(uint2*)&g_Al[idx] = make_uint2(*(uint32_t*)&l01, *(uint32_t*)&l23);
        }
#pragma unroll
        for (int o = 16; o > 0; o >>= 1) rs += __shfl_xor_sync(0xffffffffu, rs, o);
        if (lane == 0) {
            float valid = (rs != 0.f) ? 1.f : 0.f;
            g_mask[row0 + r] = valid;
            cnt += valid;
        }
    }
#pragma unroll
    for (int j = 0; j < 16; ++j) part[warp][(j >> 2) * 128 + lane * 4 + (j & 3)] = creg[j];
    if (lane == 0) cnt_sm[warp] = cnt;
    __syncthreads();

    for (int e = tid; e < EE; e += 256) {
        float s = 0.f;
#pragma unroll
        for (int w = 0; w < 8; ++w) s += part[w][e];
        g_ctxsum[blk * EE + e] = s;
    }
    if (tid == 0) {
        float s = 0.f;
#pragma unroll
        for (int w = 0; w < 8; ++w) s += cnt_sm[w];
        g_count[blk] = s;
    }
}

// ---------------------------------------------------------------------------
// Kernel B: u[b,h] = b_att[h] + (1/len) * sum_e ctxsum[b,e] * W_att[E+e, h]
// ---------------------------------------------------------------------------
__global__ void __launch_bounds__(512) u_kernel(const float* __restrict__ Watt,
                                                const float* __restrict__ b_att) {
    __shared__ float ctx[EE];
    __shared__ float leninv;
    const int b = blockIdx.x, tid = threadIdx.x;

    float s = g_ctxsum[(b * 4 + 0) * EE + tid] + g_ctxsum[(b * 4 + 1) * EE + tid] +
              g_ctxsum[(b * 4 + 2) * EE + tid] + g_ctxsum[(b * 4 + 3) * EE + tid];
    ctx[tid] = s;
    if (tid == 0) {
        float len = g_count[b * 4 + 0] + g_count[b * 4 + 1] +
                    g_count[b * 4 + 2] + g_count[b * 4 + 3];
        leninv = 1.f / len;
    }
    __syncthreads();

    const float li = leninv;
    const float* Wb = Watt + (size_t)EE * HH;
    float acc = 0.f;
    for (int e = 0; e < EE; ++e) acc += ctx[e] * Wb[(size_t)e * HH + tid];
    g_u[b * HH + tid] = b_att[tid] + li * acc;
}

// ---------------------------------------------------------------------------
// Kernel C: tensor-core scores GEMM.
// CTA tile 128x128, 128 threads (4 warps, 64x64 each), BK=32, 3-stage
// cp.async pipeline, ONE __syncthreads per chunk, 2 CTAs/SM.
// Packed BK=32 tile layout: element (r, c) at byte
//   (r>>1)*128 + ((r&1)*4 + ((c>>3) ^ ((r>>1)&3)))*16 + (c&7)*2
// -> conflict-free for both cp.async stores and ldmatrix phases.
// grid = 4096 (mt*4 + nt). 3 products Ah*Bh + Al*Bh + Ah*Bl.
// ---------------------------------------------------------------------------
#define STG_BYTES 32768
#define ST_AH 0
#define ST_AL 8192
#define ST_BH 16384
#define ST_BL 24576
#define SM_US (3 * STG_BYTES)
#define SM_VS (SM_US + 512)
#define SM_RED (SM_VS + 512)
#define SMEM_GEMM (SM_RED + 1024)

__global__ void __launch_bounds__(128, 2) scores_mma_kernel(const float* __restrict__ v) {
    extern __shared__ char smem[];
    const uint32_t sbase = smem_to_u32(smem);
    const int tid = threadIdx.x, wid = tid >> 5, lane = tid & 31;
    const int mt = blockIdx.x >> 2, nt = blockIdx.x & 3;
    const int m0 = mt * 128, n0 = nt * 128;
    const int b = m0 >> 11;

    float* u_s = (float*)(smem + SM_US);
    float* v_s = (float*)(smem + SM_VS);
    u_s[tid] = g_u[b * HH + n0 + tid];
    v_s[tid] = v[n0 + tid];

    // loader mapping: thread t -> (row = (t>>2) + 32*i, ks = t&3), 16B each
    const int lr = tid >> 2, lks = tid & 3;
    const uint32_t soff0 = (uint32_t)((lr >> 1) * 128 +
                                      (((lr & 1) * 4 + (lks ^ ((lr >> 1) & 3))) << 4));
    const __nv_bfloat16* pAh = g_Ah + (size_t)(m0 + lr) * EE + lks * 8;
    const __nv_bfloat16* pAl = g_Al + (size_t)(m0 + lr) * EE + lks * 8;
    const __nv_bfloat16* pBh = g_Wh + (size_t)(n0 + lr) * EE + lks * 8;
    const __nv_bfloat16* pBl = g_Wl + (size_t)(n0 + lr) * EE + lks * 8;

    // fragment addressing; warp tile 64(m) x 64(n): Wm=(wid>>1)*64, Wn=(wid&1)*64
    const int matrix = lane >> 3, r8 = lane & 7;
    const int Wm = (wid >> 1) * 64, Wn = (wid & 1) * 64;
    const uint32_t mkA = (uint32_t)(matrix >> 1);  // A k16-seg select
    const uint32_t mkB = (uint32_t)(matrix & 1);   // B k16-seg select
    uint32_t a_off[4], a_xm[4];
#pragma unroll
    for (int mf = 0; mf < 4; ++mf) {
        int arow = Wm + mf * 16 + r8 + (matrix & 1) * 8;
        a_off[mf] = (uint32_t)((arow >> 1) * 128 + (arow & 1) * 64);
        a_xm[mf] = (uint32_t)((arow >> 1) & 3);
    }
    uint32_t b_off[4], b_xm[4];
#pragma unroll
    for (int pr = 0; pr < 4; ++pr) {
        int nrow = Wn + pr * 16 + (matrix >> 1) * 8 + r8;
        b_off[pr] = (uint32_t)((nrow >> 1) * 128 + (nrow & 1) * 64);
        b_xm[pr] = (uint32_t)((nrow >> 1) & 3);
    }

    float acc[4][8][4];
#pragma unroll
    for (int i = 0; i < 4; ++i)
#pragma unroll
        for (int j = 0; j < 8; ++j)
#pragma unroll
            for (int q = 0; q < 4; ++q) acc[i][j][q] = 0.f;

    auto issue = [&](int c, int s) {
        const uint32_t st = sbase + (uint32_t)s * STG_BYTES;
        const int kof = c * 32;
#pragma unroll
        for (int i = 0; i < 4; ++i) {
            const uint32_t so = soff0 + (uint32_t)i * 2048;
            const size_t go = (size_t)i * 32 * EE + kof;
            cp16(st + ST_AH + so, pAh + go);
            cp16(st + ST_AL + so, pAl + go);
            cp16(st + ST_BH + so, pBh + go);
            cp16(st + ST_BL + so, pBl + go);
        }
        CP_COMMIT();
    };

    issue(0, 0);
    issue(1, 1);
#pragma unroll 1
    for (int c = 0; c < 16; ++c) {
        if (c < 15) cp_wait<1>(); else cp_wait<0>();
        __syncthreads();
        if (c < 14) issue(c + 2, (c + 2) % 3);

        const uint32_t st = sbase + (uint32_t)(c % 3) * STG_BYTES;
#pragma unroll
        for (int k16 = 0; k16 < 2; ++k16) {
            const uint32_t ksA = (uint32_t)(k16 * 2) + mkA;
            const uint32_t ksB = (uint32_t)(k16 * 2) + mkB;
            uint32_t ah[4][4], bh[4][4];
            // product 0: Ah x Bh
#pragma unroll
            for (int mf = 0; mf < 4; ++mf)
                ldsm_x4(ah[mf], st + ST_AH + a_off[mf] + ((ksA ^ a_xm[mf]) << 4));
#pragma unroll
            for (int pr = 0; pr < 4; ++pr)
                ldsm_x4(bh[pr], st + ST_BH + b_off[pr] + ((ksB ^ b_xm[pr]) << 4));
#pragma unroll
            for (int mf = 0; mf < 4; ++mf)
#pragma unroll
                for (int nf = 0; nf < 8; ++nf)
                    mma16816(acc[mf][nf], ah[mf], &bh[nf >> 1][(nf & 1) * 2]);
            // product 1: Al x Bh (reuse bh)
            {
                uint32_t al[4][4];
#pragma unroll
                for (int mf = 0; mf < 4; ++mf)
                    ldsm_x4(al[mf], st + ST_AL + a_off[mf] + ((ksA ^ a_xm[mf]) << 4));
#pragma unroll
                for (int mf = 0; mf < 4; ++mf)
#pragma unroll
                    for (int nf = 0; nf < 8; ++nf)
                        mma16816(acc[mf][nf], al[mf], &bh[nf >> 1][(nf & 1) * 2]);
            }
            // product 2: Ah x Bl (reuse ah)
            {
                uint32_t bl[4][4];
#pragma unroll
                for (int pr = 0; pr < 4; ++pr)
                    ldsm_x4(bl[pr], st + ST_BL + b_off[pr] + ((ksB ^ b_xm[pr]) << 4));
#pragma unroll
                for (int mf = 0; mf < 4; ++mf)
#pragma unroll
                    for (int nf = 0; nf < 8; ++nf)
                        mma16816(acc[mf][nf], ah[mf], &bl[nf >> 1][(nf & 1) * 2]);
            }
        }
    }
    __syncthreads();

    // epilogue: tanh + dot(v) over this CTA's 128 cols
    float* red = (float*)(smem + SM_RED);  // [128][2]
    const int g = lane >> 2, cq = (lane & 3) * 2;
#pragma unroll
    for (int mf = 0; mf < 4; ++mf) {
        float s0 = 0.f, s1 = 0.f;
#pragma unroll
        for (int nf = 0; nf < 8; ++nf) {
            const int col = Wn + nf * 8 + cq;
            const float u0 = u_s[col], u1 = u_s[col + 1];
            const float v0 = v_s[col], v1 = v_s[col + 1];
            s0 += tanhf(acc[mf][nf][0] + u0) * v0;
            s0 += tanhf(acc[mf][nf][1] + u1) * v1;
            s1 += tanhf(acc[mf][nf][2] + u0) * v0;
            s1 += tanhf(acc[mf][nf][3] + u1) * v1;
        }
        s0 += __shfl_xor_sync(0xffffffffu, s0, 1);
        s0 += __shfl_xor_sync(0xffffffffu, s0, 2);
        s1 += __shfl_xor_sync(0xffffffffu, s1, 1);
        s1 += __shfl_xor_sync(0xffffffffu, s1, 2);
        if ((lane & 3) == 0) {
            red[(Wm + mf * 16 + g) * 2 + (wid & 1)] = s0;
            red[(Wm + mf * 16 + g + 8) * 2 + (wid & 1)] = s1;
        }
    }
    __syncthreads();

    g_spart[(size_t)nt * MTOT + m0 + tid] = red[tid * 2] + red[tid * 2 + 1];
}

// ---------------------------------------------------------------------------
// Kernel D: masked softmax over S per batch (sums the 4 n-tile partials)
// ---------------------------------------------------------------------------
__global__ void __launch_bounds__(256) softmax_kernel() {
    __shared__ float redv[8];
    __shared__ float bval;
    const int b = blockIdx.x, tid = threadIdx.x;
    const int warp = tid >> 5, lane = tid & 31;

    float s[8];
    float mx = -3.4e38f;
#pragma unroll
    for (int i = 0; i < 8; ++i) {
        const int m = b * SS + tid + 256 * i;
        float sc = g_spart[m] + g_spart[MTOT + m] + g_spart[2 * MTOT + m] +
                   g_spart[3 * MTOT + m];
        s[i] = (g_mask[m] != 0.f) ? sc : -1e30f;
        mx = fmaxf(mx, s[i]);
    }
#pragma unroll
    for (int o = 16; o > 0; o >>= 1) mx = fmaxf(mx, __shfl_xor_sync(0xffffffffu, mx, o));
    if (lane == 0) redv[warp] = mx;
    __syncthreads();
    if (tid == 0) {
        float m = redv[0];
#pragma unroll
        for (int w = 1; w < 8; ++w) m = fmaxf(m, redv[w]);
        bval = m;
    }
    __syncthreads();
    mx = bval;

    float sum = 0.f;
#pragma unroll
    for (int i = 0; i < 8; ++i) {
        s[i] = expf(s[i] - mx);
        sum += s[i];
    }
#pragma unroll
    for (int o = 16; o > 0; o >>= 1) sum += __shfl_xor_sync(0xffffffffu, sum, o);
    __syncthreads();
    if (lane == 0) redv[warp] = sum;
    __syncthreads();
    if (tid == 0) {
        float t = 0.f;
#pragma unroll
        for (int w = 0; w < 8; ++w) t += redv[w];
        bval = 1.f / t;
    }
    __syncthreads();
    const float inv = bval;
#pragma unroll
    for (int i = 0; i < 8; ++i) g_attn[b * SS + tid + 256 * i] = s[i] * inv;
}

// ---------------------------------------------------------------------------
// Kernel E: partial rep
// ---------------------------------------------------------------------------
__global__ void __launch_bounds__(512) rep_kernel(const float* __restrict__ words) {
    __shared__ float a_sm[256];
    const int blk = blockIdx.x;
    const int b = blk >> 3, c = blk & 7;
    const int tid = threadIdx.x;
    if (tid < 256) a_sm[tid] = g_attn[b * SS + c * 256 + tid];
    __syncthreads();

    const float* wp = words + ((size_t)(b * SS + c * 256)) * EE + tid;
    float acc = 0.f;
#pragma unroll 4
    for (int i = 0; i < 256; ++i) acc += a_sm[i] * wp[(size_t)i * EE];
    g_rep[(size_t)blk * EE + tid] = acc;
}

// ---------------------------------------------------------------------------
// Kernel F: reduce rep partials + 3-layer MLP
// ---------------------------------------------------------------------------
__global__ void __launch_bounds__(512) mlp_kernel(const float* __restrict__ W1,
                                                  const float* __restrict__ b1,
                                                  const float* __restrict__ W2,
                                                  const float* __restrict__ b2,
                                                  const float* __restrict__ W3,
                                                  const float* __restrict__ b3,
                                                  float* __restrict__ out) {
    __shared__ float x[EE];
    __shared__ float h1[HH];
    __shared__ float h2[HH];
    const int b = blockIdx.x, tid = threadIdx.x;

    float r = 0.f;
#pragma unroll
    for (int c = 0; c < 8; ++c) r += g_rep[(size_t)(b * 8 + c) * EE + tid];
    x[tid] = r;
    __syncthreads();

    float a = b1[tid];
    for (int e = 0; e < EE; ++e) a += x[e] * W1[(size_t)e * HH + tid];
    h1[tid] = fmaxf(a, 0.f);
    __syncthreads();

    a = b2[tid];
    for (int e = 0; e < HH; ++e) a += h1[e] * W2[(size_t)e * HH + tid];
    h2[tid] = fmaxf(a, 0.f);
    __syncthreads();

    if (tid < TT) {
        a = b3[tid];
        for (int e = 0; e < HH; ++e) a += h2[e] * W3[(size_t)e * TT + tid];
        out[b * TT + tid] = a;
    }
}

// ---------------------------------------------------------------------------
extern "C" void kernel_launch(void* const* d_in, const int* in_sizes, int n_in,
                              void* d_out, int out_size) {
    const float* words = (const float*)d_in[0];
    const float* Watt  = (const float*)d_in[1];
    const float* b_att = (const float*)d_in[2];
    const float* v     = (const float*)d_in[3];
    const float* W1    = (const float*)d_in[4];
    const float* b1    = (const float*)d_in[5];
    const float* W2    = (const float*)d_in[6];
    const float* b2    = (const float*)d_in[7];
    const float* W3    = (const float*)d_in[8];
    const float* b3    = (const float*)d_in[9];
    float* out = (float*)d_out;

    cudaFuncSetAttribute(scores_mma_kernel, cudaFuncAttributeMaxDynamicSharedMemorySize,
                         SMEM_GEMM);

    wprep_kernel<<<HH, 512>>>(Watt);
    ctx_prep_kernel<<<BB * 4, 256>>>(words);
    u_kernel<<<BB, 512>>>(Watt, b_att);
    scores_mma_kernel<<<(MTOT / 128) * 4, 128, SMEM_GEMM>>>(v);
    softmax_kernel<<<BB, 256>>>();
    rep_kernel<<<BB * 8, 512>>>(words);
    mlp_kernel<<<BB, 512>>>(W1, b1, W2, b2, W3, b3, out);
}